// round 1
// baseline (speedup 1.0000x reference)
#include <cuda_runtime.h>
#include <math.h>

#define BATCH 8
#define SEQ   1024
#define DIM   1024
#define NH    16
#define HD    64
#define MROWS (BATCH*SEQ)      // 8192
#define N_QKV (3*DIM)          // 3072

// Scratch (allocation-free rule: __device__ globals)
__device__ float g_qkv[(size_t)MROWS * N_QKV];   // 96 MB
__device__ float g_attn[(size_t)MROWS * DIM];    // 32 MB

// ----------------------------------------------------------------------------
// NT GEMM: C[m,n] = sum_k A[m,k] * B[n,k] + bias[n]
// A: [M,K] row-major, B: [N,K] row-major. 128x128 tile, BK=16, 8x8 per thread.
// M,N,K all multiples of 128 here -> no bounds checks.
// ----------------------------------------------------------------------------
__global__ __launch_bounds__(256) void gemm_nt_bias(
    const float* __restrict__ A, const float* __restrict__ B,
    const float* __restrict__ bias, float* __restrict__ Cm,
    int M, int N, int K)
{
    __shared__ float As[16][132];
    __shared__ float Bs[16][132];

    const int tid = threadIdx.x;
    const int m0 = blockIdx.y * 128;
    const int n0 = blockIdx.x * 128;
    const int tx = tid & 15;       // n direction
    const int ty = tid >> 4;       // m direction

    const int lr = tid >> 2;            // 0..63 (row within tile)
    const int lc = (tid & 3) * 4;       // 0,4,8,12 (k within tile)

    const float* Aptr = A + (size_t)(m0 + lr) * K + lc;
    const float* Bptr = B + (size_t)(n0 + lr) * K + lc;
    const int rowStride = 64 * K;

    float acc[8][8];
    #pragma unroll
    for (int i = 0; i < 8; i++)
        #pragma unroll
        for (int j = 0; j < 8; j++) acc[i][j] = 0.f;

    for (int k0 = 0; k0 < K; k0 += 16) {
        float4 a0 = *(const float4*)(Aptr + k0);
        float4 a1 = *(const float4*)(Aptr + k0 + rowStride);
        float4 b0 = *(const float4*)(Bptr + k0);
        float4 b1 = *(const float4*)(Bptr + k0 + rowStride);

        As[lc+0][lr]    = a0.x; As[lc+1][lr]    = a0.y; As[lc+2][lr]    = a0.z; As[lc+3][lr]    = a0.w;
        As[lc+0][lr+64] = a1.x; As[lc+1][lr+64] = a1.y; As[lc+2][lr+64] = a1.z; As[lc+3][lr+64] = a1.w;
        Bs[lc+0][lr]    = b0.x; Bs[lc+1][lr]    = b0.y; Bs[lc+2][lr]    = b0.z; Bs[lc+3][lr]    = b0.w;
        Bs[lc+0][lr+64] = b1.x; Bs[lc+1][lr+64] = b1.y; Bs[lc+2][lr+64] = b1.z; Bs[lc+3][lr+64] = b1.w;
        __syncthreads();

        #pragma unroll
        for (int k = 0; k < 16; k++) {
            float a[8], bb[8];
            *(float4*)(a)    = *(const float4*)&As[k][ty*8];
            *(float4*)(a+4)  = *(const float4*)&As[k][ty*8+4];
            *(float4*)(bb)   = *(const float4*)&Bs[k][tx*8];
            *(float4*)(bb+4) = *(const float4*)&Bs[k][tx*8+4];
            #pragma unroll
            for (int i = 0; i < 8; i++)
                #pragma unroll
                for (int j = 0; j < 8; j++)
                    acc[i][j] = fmaf(a[i], bb[j], acc[i][j]);
        }
        __syncthreads();
    }

    // epilogue with bias
    float bv[8];
    #pragma unroll
    for (int j = 0; j < 8; j++) bv[j] = bias[n0 + tx*8 + j];

    #pragma unroll
    for (int i = 0; i < 8; i++) {
        float* crow = Cm + (size_t)(m0 + ty*8 + i) * N + n0 + tx*8;
        float4 r0 = make_float4(acc[i][0]+bv[0], acc[i][1]+bv[1], acc[i][2]+bv[2], acc[i][3]+bv[3]);
        float4 r1 = make_float4(acc[i][4]+bv[4], acc[i][5]+bv[5], acc[i][6]+bv[6], acc[i][7]+bv[7]);
        *(float4*)(crow)     = r0;
        *(float4*)(crow + 4) = r1;
    }
}

// ----------------------------------------------------------------------------
// Windowed attention. One block = (b, h, 64-query tile). Keys [q0-64, q0+127]
// (192 rows, clipped). smem: Q[64x64] + K/V[192x65] + S[64x192] + rowsum.
// ----------------------------------------------------------------------------
#define QB 192
__global__ __launch_bounds__(256) void local_attn(
    const float* __restrict__ qkv, float* __restrict__ out)
{
    extern __shared__ float sm[];
    float* Qs   = sm;                  // 64*64   = 4096
    float* KVs  = Qs + 64*64;          // 192*65  = 12480
    float* Ss   = KVs + 192*65;        // 64*192  = 12288
    float* rsum = Ss + 64*192;         // 64

    const int bh = blockIdx.x;
    const int b  = bh / NH;
    const int h  = bh % NH;
    const int q0 = blockIdx.y * 64;
    const int tid = threadIdx.x;
    const int R = N_QKV;
    const float* base = qkv + (size_t)b * SEQ * R;
    const int kbase = q0 - 64;

    // load Q tile
    for (int idx = tid; idx < 64*64; idx += 256) {
        int r = idx >> 6, d = idx & 63;
        Qs[idx] = base[(size_t)(q0 + r) * R + h*HD + d];
    }
    // load K slab (zero-fill out-of-range)
    for (int idx = tid; idx < QB*64; idx += 256) {
        int r = idx >> 6, d = idx & 63;
        int j = kbase + r;
        KVs[r*65 + d] = (j >= 0 && j < SEQ) ? base[(size_t)j * R + DIM + h*HD + d] : 0.f;
    }
    __syncthreads();

    // S = Q K^T * scale, with window mask |i-j|<=64  <=>  kk in [q, q+128]
    const float scale = 0.125f;
    for (int idx = tid; idx < 64*QB; idx += 256) {
        int q = idx / QB, kk = idx % QB;
        int j = kbase + kk;
        float s = -1e30f;
        if (kk >= q && kk <= q + 128 && j >= 0 && j < SEQ) {
            const float* qr = Qs + q*64;
            const float* kr = KVs + kk*65;
            float acc = 0.f;
            #pragma unroll
            for (int d = 0; d < 64; d++) acc = fmaf(qr[d], kr[d], acc);
            s = acc * scale;
        }
        Ss[idx] = s;
    }
    __syncthreads();

    // softmax (warp per row) -- store un-normalized exp + row sums
    {
        const int warp = tid >> 5, lane = tid & 31;
        for (int q = warp; q < 64; q += 8) {
            float* row = Ss + q*QB;
            float m = -1e30f;
            for (int kk = lane; kk < QB; kk += 32) m = fmaxf(m, row[kk]);
            #pragma unroll
            for (int o = 16; o; o >>= 1) m = fmaxf(m, __shfl_xor_sync(0xffffffffu, m, o));
            float ssum = 0.f;
            for (int kk = lane; kk < QB; kk += 32) {
                float e = __expf(row[kk] - m);
                row[kk] = e;
                ssum += e;
            }
            #pragma unroll
            for (int o = 16; o; o >>= 1) ssum += __shfl_xor_sync(0xffffffffu, ssum, o);
            if (lane == 0) rsum[q] = ssum;
        }
    }
    // load V slab into KVs (S pass done reading it; softmax touches only Ss)
    for (int idx = tid; idx < QB*64; idx += 256) {
        int r = idx >> 6, d = idx & 63;
        int j = kbase + r;
        KVs[r*65 + d] = (j >= 0 && j < SEQ) ? base[(size_t)j * R + 2*DIM + h*HD + d] : 0.f;
    }
    __syncthreads();

    // O = P V / rowsum
    for (int idx = tid; idx < 64*64; idx += 256) {
        int q = idx >> 6, d = idx & 63;
        const float* prow = Ss + q*QB;
        float acc = 0.f;
        #pragma unroll 4
        for (int kk = 0; kk < QB; kk++) acc = fmaf(prow[kk], KVs[kk*65 + d], acc);
        out[(size_t)(b*SEQ + q0 + q) * DIM + h*HD + d] = acc * (1.0f / rsum[q]);
    }
}

// ----------------------------------------------------------------------------
extern "C" void kernel_launch(void* const* d_in, const int* in_sizes, int n_in,
                              void* d_out, int out_size)
{
    const float* x   = (const float*)d_in[0];   // [8,1024,1024]
    const float* w1  = (const float*)d_in[1];   // [3072,1024]
    const float* b1  = (const float*)d_in[2];   // [3072]
    const float* w2  = (const float*)d_in[3];   // [1024,1024]
    const float* b2  = (const float*)d_in[4];   // [1024]
    float* out = (float*)d_out;

    float *qkv, *attn;
    cudaGetSymbolAddress((void**)&qkv,  g_qkv);
    cudaGetSymbolAddress((void**)&attn, g_attn);

    // GEMM1: qkv = x @ w1^T + b1   [8192, 3072]
    {
        dim3 grid(N_QKV / 128, MROWS / 128);
        gemm_nt_bias<<<grid, 256>>>(x, w1, b1, qkv, MROWS, N_QKV, DIM);
    }

    // Attention
    {
        int smem = (64*64 + 192*65 + 64*192 + 64) * (int)sizeof(float);  // ~115.7 KB
        cudaFuncSetAttribute(local_attn, cudaFuncAttributeMaxDynamicSharedMemorySize, smem);
        dim3 grid(BATCH * NH, SEQ / 64);
        local_attn<<<grid, 256, smem>>>(qkv, attn);
    }

    // GEMM2: out = attn @ w2^T + b2   [8192, 1024]
    {
        dim3 grid(DIM / 128, MROWS / 128);
        gemm_nt_bias<<<grid, 256>>>(attn, w2, b2, out, MROWS, DIM, DIM);
    }
}

// round 7
// speedup vs baseline: 1.5110x; 1.5110x over previous
#include <cuda_runtime.h>
#include <cuda_bf16.h>
#include <cstdint>
#include <math.h>

#define BATCH 8
#define SEQ   1024
#define DIM   1024
#define NH    16
#define HD    64
#define MROWS (BATCH*SEQ)      // 8192
#define N_QKV (3*DIM)          // 3072
#define K3    (3*DIM)          // 3072 (3-way bf16 split K)

// Scratch (allocation-free rule: __device__ globals)
__device__ float          g_qkv[(size_t)MROWS * N_QKV];     // 96 MB fp32
__device__ __nv_bfloat16  g_x3 [(size_t)MROWS * K3];        // 48 MB
__device__ __nv_bfloat16  g_w1b[(size_t)N_QKV * K3];        // 18 MB
__device__ __nv_bfloat16  g_w2b[(size_t)DIM   * K3];        //  6 MB
__device__ __nv_bfloat16  g_at3[(size_t)MROWS * K3];        // 48 MB

// ============================ helpers ========================================
__device__ __forceinline__ uint32_t smem_u32(const void* p) {
    uint32_t a;
    asm("{ .reg .u64 t; cvta.to.shared.u64 t, %1; cvt.u32.u64 %0, t; }"
        : "=r"(a) : "l"(p));
    return a;
}
#define CP_ASYNC16(saddr, gptr) \
    asm volatile("cp.async.cg.shared.global [%0], [%1], 16;" \
                 :: "r"(saddr), "l"(gptr) : "memory")
#define CP_COMMIT() asm volatile("cp.async.commit_group;" ::: "memory")
#define CP_WAIT(n)  asm volatile("cp.async.wait_group %0;" :: "n"(n) : "memory")

__device__ __forceinline__ void mma_bf16(float* c, const uint32_t* a, const uint32_t* b) {
    asm volatile(
        "mma.sync.aligned.m16n8k16.row.col.f32.bf16.bf16.f32 "
        "{%0,%1,%2,%3}, {%4,%5,%6,%7}, {%8,%9}, {%0,%1,%2,%3};"
        : "+f"(c[0]), "+f"(c[1]), "+f"(c[2]), "+f"(c[3])
        : "r"(a[0]), "r"(a[1]), "r"(a[2]), "r"(a[3]), "r"(b[0]), "r"(b[1]));
}

// split v into hi (bf16) and lo (bf16 of residual)
__device__ __forceinline__ void split_hl(float v, __nv_bfloat16& h, __nv_bfloat16& l) {
    h = __float2bfloat16(v);
    l = __float2bfloat16(v - __bfloat162float(h));
}

// fp32[n] -> bf16 triplets [3n].  PATTERN 0 (A side): (hi, lo, hi)
//                                 PATTERN 1 (B side): (hi, hi, lo)
template <int PATTERN>
__global__ __launch_bounds__(256) void cvt3(
    const float* __restrict__ src, __nv_bfloat16* __restrict__ dst, int n)
{
    int i = blockIdx.x * 256 + threadIdx.x;          // chunk of 8 floats
    const int stride = gridDim.x * 256;
    for (; i * 8 < n; i += stride) {
        float4 v0 = *(const float4*)(src + i * 8);
        float4 v1 = *(const float4*)(src + i * 8 + 4);
        float f[8] = { v0.x, v0.y, v0.z, v0.w, v1.x, v1.y, v1.z, v1.w };
        __align__(16) __nv_bfloat16 o[24];
        #pragma unroll
        for (int k = 0; k < 8; k++) {
            __nv_bfloat16 h, l;
            split_hl(f[k], h, l);
            o[3*k + 0] = h;
            o[3*k + 1] = (PATTERN == 0) ? l : h;
            o[3*k + 2] = (PATTERN == 0) ? h : l;
        }
        __nv_bfloat16* dp = dst + (size_t)i * 24;
        *(uint4*)(dp)      = *(uint4*)(o);
        *(uint4*)(dp + 8)  = *(uint4*)(o + 8);
        *(uint4*)(dp + 16) = *(uint4*)(o + 16);
    }
}

// ============================ bf16 mma.sync GEMM =============================
// C[m,n] = sum_k A[m,k]*B[n,k] + bias[n].  A:[M,K3], B:[N,K3] bf16 triplets.
// 128x128 tile, BK=32 bf16, 8 warps (4m x 2n), warp tile 32x64. 4-stage cp.async.
#define TM 128
#define TN 128
#define BK 32
#define STAGES 4
#define RP 40                                  // bf16 per smem row (80B, 16B aligned)
#define STAGE_ELEMS (2 * 128 * RP)             // A tile + B tile (bf16)
#define GEMM_SMEM (STAGES * STAGE_ELEMS * 2)   // 81920 B

__global__ __launch_bounds__(256) void gemm_tc(
    const __nv_bfloat16* __restrict__ A, const __nv_bfloat16* __restrict__ B,
    const float* __restrict__ bias, float* __restrict__ C,
    int N)
{
    extern __shared__ __align__(128) __nv_bfloat16 smem[];
    const int tid  = threadIdx.x;
    const int wid  = tid >> 5;
    const int lane = tid & 31;
    const int m0 = blockIdx.y * TM;
    const int n0 = blockIdx.x * TN;

    const int mbase = (wid & 3) * 32;   // warp m offset
    const int nbase = (wid >> 2) * 64;  // warp n offset
    const int g  = lane >> 2;           // 0..7
    const int tq = lane & 3;            // 0..3

    const uint32_t sbase = smem_u32(smem);

    float acc[2][8][4];
    #pragma unroll
    for (int i = 0; i < 2; i++)
        #pragma unroll
        for (int j = 0; j < 8; j++)
            #pragma unroll
            for (int v = 0; v < 4; v++) acc[i][j][v] = 0.f;

    const int nk = K3 / BK;   // 96

    // 1024 16B-chunks per stage (A 512 + B 512); 4 per thread.
    #define LOAD_STAGE(slot, kidx) do {                                          \
        const int k0_ = (kidx) * BK;                                             \
        const uint32_t st_ = sbase + (uint32_t)(slot) * STAGE_ELEMS * 2;         \
        _Pragma("unroll")                                                        \
        for (int it = 0; it < 4; it++) {                                         \
            int id = tid + it * 256;                                             \
            int isA = id < 512;                                                  \
            int loc = isA ? id : id - 512;                                       \
            int row = loc >> 2, c = loc & 3;                                     \
            const __nv_bfloat16* gp = isA                                        \
                ? (A + (size_t)(m0 + row) * K3 + k0_ + c * 8)                    \
                : (B + (size_t)(n0 + row) * K3 + k0_ + c * 8);                   \
            uint32_t sa = st_ + (uint32_t)((isA ? 0 : 128 * RP)                  \
                              + row * RP + c * 8) * 2;                           \
            CP_ASYNC16(sa, gp);                                                  \
        }                                                                        \
        CP_COMMIT();                                                             \
    } while (0)

    #pragma unroll
    for (int s = 0; s < STAGES - 1; s++) LOAD_STAGE(s, s);

    #pragma unroll 1
    for (int k = 0; k < nk; k++) {
        CP_WAIT(STAGES - 2);
        __syncthreads();

        if (k + STAGES - 1 < nk) LOAD_STAGE((k + STAGES - 1) & (STAGES - 1), k + STAGES - 1);
        else CP_COMMIT();

        const __nv_bfloat16* As = smem + (k & (STAGES - 1)) * STAGE_ELEMS;
        const __nv_bfloat16* Bs = As + 128 * RP;

        #pragma unroll
        for (int kk = 0; kk < BK; kk += 16) {
            uint32_t a[2][4], b[8][2];
            #pragma unroll
            for (int mi = 0; mi < 2; mi++) {
                const __nv_bfloat16* ap = As + (mbase + mi * 16 + g) * RP + kk + 2 * tq;
                a[mi][0] = *(const uint32_t*)(ap);            // (g,   k..k+1)
                a[mi][1] = *(const uint32_t*)(ap + 8 * RP);   // (g+8, k..k+1)
                a[mi][2] = *(const uint32_t*)(ap + 8);        // (g,   k+8..k+9)
                a[mi][3] = *(const uint32_t*)(ap + 8 * RP + 8);
            }
            #pragma unroll
            for (int ni = 0; ni < 8; ni++) {
                const __nv_bfloat16* bp = Bs + (nbase + ni * 8 + g) * RP + kk + 2 * tq;
                b[ni][0] = *(const uint32_t*)(bp);
                b[ni][1] = *(const uint32_t*)(bp + 8);
            }
            #pragma unroll
            for (int mi = 0; mi < 2; mi++)
                #pragma unroll
                for (int ni = 0; ni < 8; ni++)
                    mma_bf16(acc[mi][ni], a[mi], b[ni]);
        }
        __syncthreads();
    }

    // ---- epilogue: c0,c1 at (g, 2tq), c2,c3 at (g+8, 2tq) ----
    #pragma unroll
    for (int mi = 0; mi < 2; mi++) {
        int mr = m0 + mbase + mi * 16 + g;
        #pragma unroll
        for (int ni = 0; ni < 8; ni++) {
            int nc = n0 + nbase + ni * 8 + 2 * tq;
            float2 bv = *(const float2*)(bias + nc);
            float2 o0 = make_float2(acc[mi][ni][0] + bv.x, acc[mi][ni][1] + bv.y);
            float2 o1 = make_float2(acc[mi][ni][2] + bv.x, acc[mi][ni][3] + bv.y);
            *(float2*)(C + (size_t)mr * N + nc)       = o0;
            *(float2*)(C + (size_t)(mr + 8) * N + nc) = o1;
        }
    }
    #undef LOAD_STAGE
}

// ============================ windowed attention =============================
// One block = (b, h, 64-query tile). Keys [q0-64, q0+127] (192 rows, clipped).
// Output written as A-side bf16 triplets (hi, lo, hi) into g_at3 [MROWS, K3].
#define QB 192
__global__ __launch_bounds__(256) void local_attn(
    const float* __restrict__ qkv, __nv_bfloat16* __restrict__ out3)
{
    extern __shared__ float sm[];
    float* Qs   = sm;                  // 64*64
    float* KVs  = Qs + 64*64;          // 192*65
    float* Ss   = KVs + 192*65;        // 64*192
    float* rsum = Ss + 64*192;         // 64

    const int bh = blockIdx.x;
    const int b  = bh / NH;
    const int h  = bh % NH;
    const int q0 = blockIdx.y * 64;
    const int tid = threadIdx.x;
    const int R = N_QKV;
    const float* base = qkv + (size_t)b * SEQ * R;
    const int kbase = q0 - 64;

    for (int idx = tid; idx < 64*64; idx += 256) {
        int r = idx >> 6, d = idx & 63;
        Qs[idx] = base[(size_t)(q0 + r) * R + h*HD + d];
    }
    for (int idx = tid; idx < QB*64; idx += 256) {
        int r = idx >> 6, d = idx & 63;
        int j = kbase + r;
        KVs[r*65 + d] = (j >= 0 && j < SEQ) ? base[(size_t)j * R + DIM + h*HD + d] : 0.f;
    }
    __syncthreads();

    const float scale = 0.125f;
    for (int idx = tid; idx < 64*QB; idx += 256) {
        int q = idx / QB, kk = idx % QB;
        int j = kbase + kk;
        float s = -1e30f;
        if (kk >= q && kk <= q + 128 && j >= 0 && j < SEQ) {
            const float* qr = Qs + q*64;
            const float* kr = KVs + kk*65;
            float acc = 0.f;
            #pragma unroll
            for (int d = 0; d < 64; d++) acc = fmaf(qr[d], kr[d], acc);
            s = acc * scale;
        }
        Ss[idx] = s;
    }
    __syncthreads();

    {
        const int warp = tid >> 5, lane = tid & 31;
        for (int q = warp; q < 64; q += 8) {
            float* row = Ss + q*QB;
            float m = -1e30f;
            for (int kk = lane; kk < QB; kk += 32) m = fmaxf(m, row[kk]);
            #pragma unroll
            for (int o = 16; o; o >>= 1) m = fmaxf(m, __shfl_xor_sync(0xffffffffu, m, o));
            float ssum = 0.f;
            for (int kk = lane; kk < QB; kk += 32) {
                float e = __expf(row[kk] - m);
                row[kk] = e;
                ssum += e;
            }
            #pragma unroll
            for (int o = 16; o; o >>= 1) ssum += __shfl_xor_sync(0xffffffffu, ssum, o);
            if (lane == 0) rsum[q] = ssum;
        }
    }
    for (int idx = tid; idx < QB*64; idx += 256) {
        int r = idx >> 6, d = idx & 63;
        int j = kbase + r;
        KVs[r*65 + d] = (j >= 0 && j < SEQ) ? base[(size_t)j * R + 2*DIM + h*HD + d] : 0.f;
    }
    __syncthreads();

    for (int idx = tid; idx < 64*64; idx += 256) {
        int q = idx >> 6, d = idx & 63;
        const float* prow = Ss + q*QB;
        float acc = 0.f;
        #pragma unroll 4
        for (int kk = 0; kk < QB; kk++) acc = fmaf(prow[kk], KVs[kk*65 + d], acc);
        float o = acc * (1.0f / rsum[q]);
        __nv_bfloat16 hi, lo;
        split_hl(o, hi, lo);
        __nv_bfloat16* dp = out3 + (size_t)(b*SEQ + q0 + q) * K3 + (h*HD + d) * 3;
        dp[0] = hi; dp[1] = lo; dp[2] = hi;
    }
}

// ----------------------------------------------------------------------------
extern "C" void kernel_launch(void* const* d_in, const int* in_sizes, int n_in,
                              void* d_out, int out_size)
{
    const float* x   = (const float*)d_in[0];   // [8,1024,1024]
    const float* w1  = (const float*)d_in[1];   // [3072,1024]
    const float* b1  = (const float*)d_in[2];   // [3072]
    const float* w2  = (const float*)d_in[3];   // [1024,1024]
    const float* b2  = (const float*)d_in[4];   // [1024]
    float* out = (float*)d_out;

    float *qkv; __nv_bfloat16 *x3, *w1b, *w2b, *at3;
    cudaGetSymbolAddress((void**)&qkv, g_qkv);
    cudaGetSymbolAddress((void**)&x3,  g_x3);
    cudaGetSymbolAddress((void**)&w1b, g_w1b);
    cudaGetSymbolAddress((void**)&w2b, g_w2b);
    cudaGetSymbolAddress((void**)&at3, g_at3);

    // precision pre-pass: fp32 -> bf16 triplets
    cvt3<0><<<2048, 256>>>(x,  x3,  MROWS * DIM);   // A side: (hi, lo, hi)
    cvt3<1><<<1024, 256>>>(w1, w1b, N_QKV * DIM);   // B side: (hi, hi, lo)
    cvt3<1><<<512,  256>>>(w2, w2b, DIM * DIM);

    cudaFuncSetAttribute(gemm_tc, cudaFuncAttributeMaxDynamicSharedMemorySize, GEMM_SMEM);

    // GEMM1: qkv = x @ w1^T + b1   [8192, 3072]
    {
        dim3 grid(N_QKV / TN, MROWS / TM);   // (24, 64)
        gemm_tc<<<grid, 256, GEMM_SMEM>>>(x3, w1b, b1, qkv, N_QKV);
    }

    // Attention (writes bf16 triplets directly)
    {
        int smem = (64*64 + 192*65 + 64*192 + 64) * (int)sizeof(float);  // ~115.7 KB
        cudaFuncSetAttribute(local_attn, cudaFuncAttributeMaxDynamicSharedMemorySize, smem);
        dim3 grid(BATCH * NH, SEQ / 64);
        local_attn<<<grid, 256, smem>>>(qkv, at3);
    }

    // GEMM2: out = attn @ w2^T + b2   [8192, 1024]
    {
        dim3 grid(DIM / TN, MROWS / TM);     // (8, 64)
        gemm_tc<<<grid, 256, GEMM_SMEM>>>(at3, w2b, b2, out, DIM);
    }
}